// round 8
// baseline (speedup 1.0000x reference)
#include <cuda_runtime.h>
#include <cstdint>
#include <math.h>

// AFMADEBlock: incremental triangular evaluation of the MADE autoregressive
// inverse. One degree-group finalized per step (31 steps).
//
// R8: net-split pairs kept (halved per-warp weight LDS), RPW 8->4 so regs
// fit 16 warps/SM (4 blocks x 128 thr, grid 512). R7 showed ~1600cyc/step
// exposed latency at 2 warps/SMSP; this doubles warps/SMSP at a crossbar
// level (~1550cyc/SM/step) still below saturation.

#define Dd 32
#define Bb 4096
#define EPSf 1e-12f
#define RPW 4                  // rows per warp pair
#define NPAIR 2                // warp pairs per block
#define NWARP (2 * NPAIR)      // 4 warps
#define THREADS (NWARP * 32)   // 128
#define ROWS_PER_BLOCK (NPAIR * RPW)   // 8
#define GRID (Bb / ROWS_PER_BLOCK)     // 512

// Permuted+masked weights (hidden units sorted by degree). ~656KB, static.
__device__ __align__(16) float g_W0p[2][32][256];
__device__ __align__(16) float g_W1p[2][256][256];
__device__ __align__(16) float g_W2p[2][256][32];
__device__ __align__(16) float g_b0p[2][256];
__device__ __align__(16) float g_b1p[2][256];
__device__ __align__(16) float g_b2[2][32];

// deg(i) = (i % 31) + 1 for original hidden index i.
// Sorted order: degrees 1..8 have 9 units, degrees 9..31 have 8 units.
__device__ __forceinline__ int degS(int k) {
    return (k < 72) ? (k / 9 + 1) : ((k - 72) / 8 + 9);
}
__device__ __forceinline__ int permS(int k) {
    int d, jj;
    if (k < 72) { d = k / 9 + 1;        jj = k % 9; }
    else        { d = (k - 72) / 8 + 9; jj = (k - 72) % 8; }
    return (d - 1) + 31 * jj;   // original index of k-th sorted unit
}

__global__ void prep_kernel(
    const float* __restrict__ mu_W0, const float* __restrict__ mu_b0,
    const float* __restrict__ mu_W1, const float* __restrict__ mu_b1,
    const float* __restrict__ mu_W2, const float* __restrict__ mu_b2,
    const float* __restrict__ lv_W0, const float* __restrict__ lv_b0,
    const float* __restrict__ lv_W1, const float* __restrict__ lv_b1,
    const float* __restrict__ lv_W2, const float* __restrict__ lv_b2)
{
    int idx = blockIdx.x * blockDim.x + threadIdx.x;
    if (idx >= 2 * 256 * 256) return;
    int net = idx >> 16;
    int k   = (idx >> 8) & 255;   // sorted hidden row
    int c   = idx & 255;          // sorted hidden col

    const float* W0 = net ? lv_W0 : mu_W0;
    const float* b0 = net ? lv_b0 : mu_b0;
    const float* W1 = net ? lv_W1 : mu_W1;
    const float* b1 = net ? lv_b1 : mu_b1;
    const float* W2 = net ? lv_W2 : mu_W2;
    const float* b2 = net ? lv_b2 : mu_b2;

    int dk = degS(k), pk = permS(k);
    int dc = degS(c), pc = permS(c);

    g_W1p[net][k][c] = (dc >= dk) ? W1[pk * 256 + pc] : 0.f;
    if (k < 32) g_W0p[net][k][c] = (dc >= (k + 1)) ? W0[k * 256 + pc] : 0.f;
    if (c < 32) g_W2p[net][k][c] = ((c + 1) > dk) ? W2[pk * 32 + c] : 0.f;
    if (k == 0) {
        g_b0p[net][c] = b0[pc];
        g_b1p[net][c] = b1[pc];
        if (c < 32) g_b2[net][c] = b2[c];
    }
}

__device__ __forceinline__ void cp16(void* s, const void* g) {
    unsigned int sa = (unsigned int)__cvta_generic_to_shared(s);
    asm volatile("cp.async.cg.shared.global [%0], [%1], 16;" :: "r"(sa), "l"(g));
}
__device__ __forceinline__ void cp_commit() {
    asm volatile("cp.async.commit_group;");
}
__device__ __forceinline__ void cp_wait_all() {
    asm volatile("cp.async.wait_group 0;");
}

// Packed dual-fp32 FMA: d = a*b + d (elementwise on the two f32 halves).
__device__ __forceinline__ void ffma2(float2& d, const float2& a, const float2& b) {
    asm("fma.rn.f32x2 %0, %1, %2, %0;"
        : "+l"(reinterpret_cast<unsigned long long&>(d))
        : "l"(reinterpret_cast<const unsigned long long&>(a)),
          "l"(reinterpret_cast<const unsigned long long&>(b)));
}

// One degree-group step for ONE net over RPW=4 rows.
// Lane l owns cols 64e+2l+{0,1}, e in [E0,4). CNT = group size, E0 = off>>6.
template<int CNT, int E0>
__device__ __forceinline__ void do_step(
    int l, int off, int buf, int net, const float2 y2[RPW],
    float2 a0[RPW][4], float2 a1[RPW][4], float2 aout2[2],
    const float* SW0, const float* SW1, const float* SW2,
    float2 (*sH0)[RPW], float (*sH1)[RPW])
{
    const float* W0 = SW0 + (buf * 2 + net) * 256;
    // ---- layer 0: a0 += y_j * W0row ----
#pragma unroll
    for (int e = E0; e < 4; e++) {
        float2 wv = *(const float2*)(W0 + 64 * e + 2 * l);
#pragma unroll
        for (int r = 0; r < RPW; r++) ffma2(a0[r][e], wv, y2[r]);
    }
    // finalize h0 group [off, off+CNT): owner lane stores {h,h} per row
#pragma unroll
    for (int e = E0; e < 4; e++) {
        int u0 = 64 * e + 2 * l - off;
        if (u0 >= 0 && u0 < CNT) {
#pragma unroll
            for (int r = 0; r < RPW; r++) {
                float h = fmaxf(a0[r][e].x, 0.f);
                sH0[u0][r] = make_float2(h, h);
            }
        }
        if (u0 + 1 >= 0 && u0 + 1 < CNT) {
#pragma unroll
            for (int r = 0; r < RPW; r++) {
                float h = fmaxf(a0[r][e].y, 0.f);
                sH0[u0 + 1][r] = make_float2(h, h);
            }
        }
    }
    __syncwarp();

    // ---- layer 1: a1 += h0_group @ W1 rows ----
#pragma unroll
    for (int u = 0; u < CNT; u++) {
        const float* wr = SW1 + ((buf * 2 + net) * 9 + u) * 256;
        float2 wv[4];
#pragma unroll
        for (int e = E0; e < 4; e++)
            wv[e] = *(const float2*)(wr + 64 * e + 2 * l);
        float4 hq0 = *(const float4*)&sH0[u][0];  // {h0,h0,h1,h1}
        float4 hq1 = *(const float4*)&sH0[u][2];  // {h2,h2,h3,h3}
        float2 h0 = make_float2(hq0.x, hq0.y);
        float2 h1 = make_float2(hq0.z, hq0.w);
        float2 h2 = make_float2(hq1.x, hq1.y);
        float2 h3 = make_float2(hq1.z, hq1.w);
#pragma unroll
        for (int e = E0; e < 4; e++) {
            ffma2(a1[0][e], wv[e], h0);
            ffma2(a1[1][e], wv[e], h1);
            ffma2(a1[2][e], wv[e], h2);
            ffma2(a1[3][e], wv[e], h3);
        }
    }
    // finalize h1 group: owner lane stores scalar h per row
#pragma unroll
    for (int e = E0; e < 4; e++) {
        int u0 = 64 * e + 2 * l - off;
        if (u0 >= 0 && u0 < CNT) {
#pragma unroll
            for (int r = 0; r < RPW; r++)
                sH1[u0][r] = fmaxf(a1[r][e].x, 0.f);
        }
        if (u0 + 1 >= 0 && u0 + 1 < CNT) {
#pragma unroll
            for (int r = 0; r < RPW; r++)
                sH1[u0 + 1][r] = fmaxf(a1[r][e].y, 0.f);
        }
    }
    __syncwarp();

    // ---- layer 2: aout += h1_group @ W2 rows (row-pair packed) ----
#pragma unroll
    for (int u = 0; u < CNT; u++) {
        float wf = SW2[((buf * 2 + net) * 9 + u) * 32 + l];
        float2 w2 = make_float2(wf, wf);
        float4 hA = *(const float4*)&sH1[u][0];   // rows 0..3
        ffma2(aout2[0], make_float2(hA.x, hA.y), w2);
        ffma2(aout2[1], make_float2(hA.z, hA.w), w2);
    }
}

// Prefetch weights for a step (row j, group offset off) into buffer buf.
// Only alive columns [64*E0, 256) are fetched. Both nets staged per block.
template<int CNT, int E0>
__device__ __forceinline__ void prefetch_step(
    int j, int off, int tid, int buf,
    float* SW0, float* SW1, float* SW2)
{
    constexpr int KC = 64 - 16 * E0;   // 16B chunks per W0/W1 row
#pragma unroll
    for (int net = 0; net < 2; net++) {
        if (tid < KC)
            cp16(SW0 + (buf * 2 + net) * 256 + 64 * E0 + 4 * tid,
                 &g_W0p[net][j][64 * E0 + 4 * tid]);
        for (int i = tid; i < CNT * KC; i += THREADS) {
            int u = i / KC, q = i % KC;
            cp16(SW1 + ((buf * 2 + net) * 9 + u) * 256 + 64 * E0 + 4 * q,
                 &g_W1p[net][off + u][64 * E0 + 4 * q]);
        }
        for (int i = tid; i < CNT * 8; i += THREADS) {
            int u = i >> 3, q = i & 7;
            cp16(SW2 + ((buf * 2 + net) * 9 + u) * 32 + 4 * q,
                 &g_W2p[net][off + u][4 * q]);
        }
    }
}

__global__ __launch_bounds__(THREADS, 4)
void afmade_kernel(const float* __restrict__ x, float* __restrict__ out)
{
    // dynamic smem: SW0 [2buf][2net][256] | SW1 [2][2][9][256] | SW2 [2][2][9][32]
    extern __shared__ __align__(16) unsigned char dynsm[];
    float* SW0 = (float*)dynsm;          // 1024 floats
    float* SW1 = SW0 + 1024;             // 9216 floats
    float* SW2 = SW1 + 9216;             // 1152 floats

    __shared__ __align__(16) float2 sH0s[NWARP][9][RPW];  // per-warp h0 {h,h}
    __shared__ __align__(16) float  sH1s[NWARP][9][RPW];  // per-warp h1 scalar
    __shared__ __align__(16) float2 sD[2][NPAIR][2];      // (x - mu) row pairs
    __shared__ __align__(16) float2 sI[2][NPAIR][2];      // 1/(exp(ls)+eps)

    const int tid  = threadIdx.x;
    const int w    = tid >> 5;
    const int l    = tid & 31;
    const int pair = w >> 1;
    const int net  = w & 1;          // 0 = mu, 1 = lv
    const int base_row = blockIdx.x * ROWS_PER_BLOCK + pair * RPW;

    float2 a0[RPW][4], a1[RPW][4], aout2[2];
    float2 xr2[2], lssum2[2];

#pragma unroll
    for (int e = 0; e < 4; e++) {
        float2 b0v = *(const float2*)&g_b0p[net][64 * e + 2 * l];
        float2 b1v = *(const float2*)&g_b1p[net][64 * e + 2 * l];
#pragma unroll
        for (int r = 0; r < RPW; r++) { a0[r][e] = b0v; a1[r][e] = b1v; }
    }
    {
        float b2v = g_b2[net][l];
        aout2[0] = make_float2(b2v, b2v);
        aout2[1] = make_float2(b2v, b2v);
    }
#pragma unroll
    for (int rp = 0; rp < 2; rp++) {
        lssum2[rp] = make_float2(0.f, 0.f);
        xr2[rp] = make_float2(x[(base_row + 2 * rp) * 32 + l],
                              x[(base_row + 2 * rp + 1) * 32 + l]);
    }

    // Prologue: prefetch step 1 into buffer 0.
    prefetch_step<9, 0>(0, 0, tid, 0, SW0, SW1, SW2);
    cp_commit();

    int buf = 0;
    for (int t = 1; t <= 32; ++t) {
        const int j = t - 1;
        const int tb = t & 1;
        // ---- emit exchange: lane j publishes its net's contribution ----
        if (l == j) {
            if (net == 0) {
#pragma unroll
                for (int rp = 0; rp < 2; rp++)
                    sD[tb][pair][rp] = make_float2(xr2[rp].x - aout2[rp].x,
                                                   xr2[rp].y - aout2[rp].y);
            } else {
#pragma unroll
                for (int rp = 0; rp < 2; rp++) {
                    float2 ls = make_float2(0.5f * aout2[rp].x, 0.5f * aout2[rp].y);
                    lssum2[rp].x += ls.x;
                    lssum2[rp].y += ls.y;
                    sI[tb][pair][rp] = make_float2(
                        __fdividef(1.f, __expf(ls.x) + EPSf),
                        __fdividef(1.f, __expf(ls.y) + EPSf));
                }
            }
        }

        cp_wait_all();
        __syncthreads();   // weights for step t ready + exchange visible

        // ---- everyone computes y for the 4 rows (broadcast LDS reads) ----
        const float* pD = (const float*)&sD[tb][pair][0];
        const float* pI = (const float*)&sI[tb][pair][0];
        float2 y2[RPW];
        {
            float4 d0 = ((const float4*)pD)[0];
            float4 i0 = ((const float4*)pI)[0];
            float yv[RPW] = {d0.x * i0.x, d0.y * i0.y, d0.z * i0.z, d0.w * i0.w};
#pragma unroll
            for (int r = 0; r < RPW; r++) y2[r] = make_float2(yv[r], yv[r]);
        }
        // mu-warp lanes 0..3 store y for their row
        if (net == 0 && l < RPW)
            out[(base_row + l) * 32 + j] = pD[l] * pI[l];

        if (t == 32) break;

        if (t < 31) {
            const int tn = t + 1, jn = tn - 1;
            const int offn = (tn <= 9) ? 9 * (tn - 1) : 72 + 8 * (tn - 9);
            if (tn <= 8)       prefetch_step<9, 0>(jn, offn, tid, buf ^ 1, SW0, SW1, SW2);
            else if (tn <= 15) prefetch_step<8, 1>(jn, offn, tid, buf ^ 1, SW0, SW1, SW2);
            else if (tn <= 23) prefetch_step<8, 2>(jn, offn, tid, buf ^ 1, SW0, SW1, SW2);
            else               prefetch_step<8, 3>(jn, offn, tid, buf ^ 1, SW0, SW1, SW2);
            cp_commit();
        }

        const int off = (t <= 9) ? 9 * (t - 1) : 72 + 8 * (t - 9);
        if (t <= 8)
            do_step<9, 0>(l, off, buf, net, y2, a0, a1, aout2, SW0, SW1, SW2, sH0s[w], sH1s[w]);
        else if (t <= 15)
            do_step<8, 1>(l, off, buf, net, y2, a0, a1, aout2, SW0, SW1, SW2, sH0s[w], sH1s[w]);
        else if (t <= 23)
            do_step<8, 2>(l, off, buf, net, y2, a0, a1, aout2, SW0, SW1, SW2, sH0s[w], sH1s[w]);
        else
            do_step<8, 3>(l, off, buf, net, y2, a0, a1, aout2, SW0, SW1, SW2, sH0s[w], sH1s[w]);
        buf ^= 1;
    }

    // ---- logstd row-sums: lv-warp reduces lane-partial sums ----
    if (net == 1) {
#pragma unroll
        for (int rp = 0; rp < 2; rp++) {
            float sx = lssum2[rp].x, sy = lssum2[rp].y;
#pragma unroll
            for (int o = 16; o > 0; o >>= 1) {
                sx += __shfl_xor_sync(0xffffffffu, sx, o);
                sy += __shfl_xor_sync(0xffffffffu, sy, o);
            }
            if (l == 0) {
                out[Bb * Dd + base_row + 2 * rp]     = sx;
                out[Bb * Dd + base_row + 2 * rp + 1] = sy;
            }
        }
    }
}

extern "C" void kernel_launch(void* const* d_in, const int* in_sizes, int n_in,
                              void* d_out, int out_size)
{
    (void)in_sizes; (void)n_in; (void)out_size;
    const float* x = (const float*)d_in[0];

    prep_kernel<<<512, 256>>>(
        (const float*)d_in[1],  (const float*)d_in[2],  (const float*)d_in[3],
        (const float*)d_in[4],  (const float*)d_in[5],  (const float*)d_in[6],
        (const float*)d_in[7],  (const float*)d_in[8],  (const float*)d_in[9],
        (const float*)d_in[10], (const float*)d_in[11], (const float*)d_in[12]);

    const int dyn_smem = (1024 + 9216 + 1152) * 4;   // 45568 B
    cudaFuncSetAttribute(afmade_kernel,
                         cudaFuncAttributeMaxDynamicSharedMemorySize, dyn_smem);
    afmade_kernel<<<GRID, THREADS, dyn_smem>>>(x, (float*)d_out);
}

// round 9
// speedup vs baseline: 1.0728x; 1.0728x over previous
#include <cuda_runtime.h>
#include <cstdint>
#include <math.h>

// AFMADEBlock: incremental triangular evaluation of the MADE autoregressive
// inverse. One degree-group finalized per step (31 steps).
//
// R9: hybrid of R5/R7/R8 lessons. Net-split warp pairs (halved per-warp
// weight LDS), RPW=4 (regs ~128), 256-thread blocks (4 pairs), grid 256.
// -> 16 warps/SM (R8's latency hiding) at R5's prefetch amortization
// (256 blocks, not 512) and R5's per-SM crossbar load. R8 failed only on
// duplicated prefetch/emit overhead from 512 blocks.

#define Dd 32
#define Bb 4096
#define EPSf 1e-12f
#define RPW 4                  // rows per warp pair
#define NPAIR 4                // warp pairs per block
#define NWARP (2 * NPAIR)      // 8 warps
#define THREADS (NWARP * 32)   // 256
#define ROWS_PER_BLOCK (NPAIR * RPW)   // 16
#define GRID (Bb / ROWS_PER_BLOCK)     // 256

// Permuted+masked weights (hidden units sorted by degree). ~656KB, static.
__device__ __align__(16) float g_W0p[2][32][256];
__device__ __align__(16) float g_W1p[2][256][256];
__device__ __align__(16) float g_W2p[2][256][32];
__device__ __align__(16) float g_b0p[2][256];
__device__ __align__(16) float g_b1p[2][256];
__device__ __align__(16) float g_b2[2][32];

// deg(i) = (i % 31) + 1 for original hidden index i.
// Sorted order: degrees 1..8 have 9 units, degrees 9..31 have 8 units.
__device__ __forceinline__ int degS(int k) {
    return (k < 72) ? (k / 9 + 1) : ((k - 72) / 8 + 9);
}
__device__ __forceinline__ int permS(int k) {
    int d, jj;
    if (k < 72) { d = k / 9 + 1;        jj = k % 9; }
    else        { d = (k - 72) / 8 + 9; jj = (k - 72) % 8; }
    return (d - 1) + 31 * jj;   // original index of k-th sorted unit
}

__global__ void prep_kernel(
    const float* __restrict__ mu_W0, const float* __restrict__ mu_b0,
    const float* __restrict__ mu_W1, const float* __restrict__ mu_b1,
    const float* __restrict__ mu_W2, const float* __restrict__ mu_b2,
    const float* __restrict__ lv_W0, const float* __restrict__ lv_b0,
    const float* __restrict__ lv_W1, const float* __restrict__ lv_b1,
    const float* __restrict__ lv_W2, const float* __restrict__ lv_b2)
{
    int idx = blockIdx.x * blockDim.x + threadIdx.x;
    if (idx >= 2 * 256 * 256) return;
    int net = idx >> 16;
    int k   = (idx >> 8) & 255;   // sorted hidden row
    int c   = idx & 255;          // sorted hidden col

    const float* W0 = net ? lv_W0 : mu_W0;
    const float* b0 = net ? lv_b0 : mu_b0;
    const float* W1 = net ? lv_W1 : mu_W1;
    const float* b1 = net ? lv_b1 : mu_b1;
    const float* W2 = net ? lv_W2 : mu_W2;
    const float* b2 = net ? lv_b2 : mu_b2;

    int dk = degS(k), pk = permS(k);
    int dc = degS(c), pc = permS(c);

    g_W1p[net][k][c] = (dc >= dk) ? W1[pk * 256 + pc] : 0.f;
    if (k < 32) g_W0p[net][k][c] = (dc >= (k + 1)) ? W0[k * 256 + pc] : 0.f;
    if (c < 32) g_W2p[net][k][c] = ((c + 1) > dk) ? W2[pk * 32 + c] : 0.f;
    if (k == 0) {
        g_b0p[net][c] = b0[pc];
        g_b1p[net][c] = b1[pc];
        if (c < 32) g_b2[net][c] = b2[c];
    }
}

__device__ __forceinline__ void cp16(void* s, const void* g) {
    unsigned int sa = (unsigned int)__cvta_generic_to_shared(s);
    asm volatile("cp.async.cg.shared.global [%0], [%1], 16;" :: "r"(sa), "l"(g));
}
__device__ __forceinline__ void cp_commit() {
    asm volatile("cp.async.commit_group;");
}
__device__ __forceinline__ void cp_wait_all() {
    asm volatile("cp.async.wait_group 0;");
}

// Packed dual-fp32 FMA: d = a*b + d (elementwise on the two f32 halves).
__device__ __forceinline__ void ffma2(float2& d, const float2& a, const float2& b) {
    asm("fma.rn.f32x2 %0, %1, %2, %0;"
        : "+l"(reinterpret_cast<unsigned long long&>(d))
        : "l"(reinterpret_cast<const unsigned long long&>(a)),
          "l"(reinterpret_cast<const unsigned long long&>(b)));
}

// One degree-group step for ONE net over RPW=4 rows.
// Lane l owns cols 64e+2l+{0,1}, e in [E0,4). CNT = group size, E0 = off>>6.
template<int CNT, int E0>
__device__ __forceinline__ void do_step(
    int l, int off, int buf, int net, const float2 y2[RPW],
    float2 a0[RPW][4], float2 a1[RPW][4], float2 aout2[2],
    const float* SW0, const float* SW1, const float* SW2,
    float2 (*sH0)[RPW], float (*sH1)[RPW])
{
    const float* W0 = SW0 + (buf * 2 + net) * 256;
    // ---- layer 0: a0 += y_j * W0row ----
#pragma unroll
    for (int e = E0; e < 4; e++) {
        float2 wv = *(const float2*)(W0 + 64 * e + 2 * l);
#pragma unroll
        for (int r = 0; r < RPW; r++) ffma2(a0[r][e], wv, y2[r]);
    }
    // finalize h0 group [off, off+CNT): owner lane stores {h,h} per row
#pragma unroll
    for (int e = E0; e < 4; e++) {
        int u0 = 64 * e + 2 * l - off;
        if (u0 >= 0 && u0 < CNT) {
#pragma unroll
            for (int r = 0; r < RPW; r++) {
                float h = fmaxf(a0[r][e].x, 0.f);
                sH0[u0][r] = make_float2(h, h);
            }
        }
        if (u0 + 1 >= 0 && u0 + 1 < CNT) {
#pragma unroll
            for (int r = 0; r < RPW; r++) {
                float h = fmaxf(a0[r][e].y, 0.f);
                sH0[u0 + 1][r] = make_float2(h, h);
            }
        }
    }
    __syncwarp();

    // ---- layer 1: a1 += h0_group @ W1 rows ----
#pragma unroll
    for (int u = 0; u < CNT; u++) {
        const float* wr = SW1 + ((buf * 2 + net) * 9 + u) * 256;
        float2 wv[4];
#pragma unroll
        for (int e = E0; e < 4; e++)
            wv[e] = *(const float2*)(wr + 64 * e + 2 * l);
        float4 hq0 = *(const float4*)&sH0[u][0];  // {h0,h0,h1,h1}
        float4 hq1 = *(const float4*)&sH0[u][2];  // {h2,h2,h3,h3}
        float2 h0 = make_float2(hq0.x, hq0.y);
        float2 h1 = make_float2(hq0.z, hq0.w);
        float2 h2 = make_float2(hq1.x, hq1.y);
        float2 h3 = make_float2(hq1.z, hq1.w);
#pragma unroll
        for (int e = E0; e < 4; e++) {
            ffma2(a1[0][e], wv[e], h0);
            ffma2(a1[1][e], wv[e], h1);
            ffma2(a1[2][e], wv[e], h2);
            ffma2(a1[3][e], wv[e], h3);
        }
    }
    // finalize h1 group: owner lane stores scalar h per row
#pragma unroll
    for (int e = E0; e < 4; e++) {
        int u0 = 64 * e + 2 * l - off;
        if (u0 >= 0 && u0 < CNT) {
#pragma unroll
            for (int r = 0; r < RPW; r++)
                sH1[u0][r] = fmaxf(a1[r][e].x, 0.f);
        }
        if (u0 + 1 >= 0 && u0 + 1 < CNT) {
#pragma unroll
            for (int r = 0; r < RPW; r++)
                sH1[u0 + 1][r] = fmaxf(a1[r][e].y, 0.f);
        }
    }
    __syncwarp();

    // ---- layer 2: aout += h1_group @ W2 rows (row-pair packed) ----
#pragma unroll
    for (int u = 0; u < CNT; u++) {
        float wf = SW2[((buf * 2 + net) * 9 + u) * 32 + l];
        float2 w2 = make_float2(wf, wf);
        float4 hA = *(const float4*)&sH1[u][0];   // rows 0..3
        ffma2(aout2[0], make_float2(hA.x, hA.y), w2);
        ffma2(aout2[1], make_float2(hA.z, hA.w), w2);
    }
}

// Prefetch weights for a step (row j, group offset off) into buffer buf.
// Only alive columns [64*E0, 256) are fetched. Both nets staged per block.
template<int CNT, int E0>
__device__ __forceinline__ void prefetch_step(
    int j, int off, int tid, int buf,
    float* SW0, float* SW1, float* SW2)
{
    constexpr int KC = 64 - 16 * E0;   // 16B chunks per W0/W1 row
#pragma unroll
    for (int net = 0; net < 2; net++) {
        if (tid < KC)
            cp16(SW0 + (buf * 2 + net) * 256 + 64 * E0 + 4 * tid,
                 &g_W0p[net][j][64 * E0 + 4 * tid]);
        for (int i = tid; i < CNT * KC; i += THREADS) {
            int u = i / KC, q = i % KC;
            cp16(SW1 + ((buf * 2 + net) * 9 + u) * 256 + 64 * E0 + 4 * q,
                 &g_W1p[net][off + u][64 * E0 + 4 * q]);
        }
        if (tid < CNT * 8) {
            int u = tid >> 3, q = tid & 7;
            cp16(SW2 + ((buf * 2 + net) * 9 + u) * 32 + 4 * q,
                 &g_W2p[net][off + u][4 * q]);
        }
    }
}

__global__ __launch_bounds__(THREADS, 2)
void afmade_kernel(const float* __restrict__ x, float* __restrict__ out)
{
    // dynamic smem: SW0 [2buf][2net][256] | SW1 [2][2][9][256] | SW2 [2][2][9][32]
    extern __shared__ __align__(16) unsigned char dynsm[];
    float* SW0 = (float*)dynsm;          // 1024 floats
    float* SW1 = SW0 + 1024;             // 9216 floats
    float* SW2 = SW1 + 9216;             // 1152 floats

    __shared__ __align__(16) float2 sH0s[NWARP][9][RPW];  // per-warp h0 {h,h}
    __shared__ __align__(16) float  sH1s[NWARP][9][RPW];  // per-warp h1 scalar
    __shared__ __align__(16) float2 sD[2][NPAIR][2];      // (x - mu) row pairs
    __shared__ __align__(16) float2 sI[2][NPAIR][2];      // 1/(exp(ls)+eps)

    const int tid  = threadIdx.x;
    const int w    = tid >> 5;
    const int l    = tid & 31;
    const int pair = w >> 1;
    const int net  = w & 1;          // 0 = mu, 1 = lv
    const int base_row = blockIdx.x * ROWS_PER_BLOCK + pair * RPW;

    float2 a0[RPW][4], a1[RPW][4], aout2[2];
    float2 xr2[2], lssum2[2];

#pragma unroll
    for (int e = 0; e < 4; e++) {
        float2 b0v = *(const float2*)&g_b0p[net][64 * e + 2 * l];
        float2 b1v = *(const float2*)&g_b1p[net][64 * e + 2 * l];
#pragma unroll
        for (int r = 0; r < RPW; r++) { a0[r][e] = b0v; a1[r][e] = b1v; }
    }
    {
        float b2v = g_b2[net][l];
        aout2[0] = make_float2(b2v, b2v);
        aout2[1] = make_float2(b2v, b2v);
    }
#pragma unroll
    for (int rp = 0; rp < 2; rp++) {
        lssum2[rp] = make_float2(0.f, 0.f);
        xr2[rp] = make_float2(x[(base_row + 2 * rp) * 32 + l],
                              x[(base_row + 2 * rp + 1) * 32 + l]);
    }

    // Prologue: prefetch step 1 into buffer 0.
    prefetch_step<9, 0>(0, 0, tid, 0, SW0, SW1, SW2);
    cp_commit();

    int buf = 0;
    for (int t = 1; t <= 32; ++t) {
        const int j = t - 1;
        const int tb = t & 1;
        // ---- emit exchange: lane j publishes its net's contribution ----
        if (l == j) {
            if (net == 0) {
#pragma unroll
                for (int rp = 0; rp < 2; rp++)
                    sD[tb][pair][rp] = make_float2(xr2[rp].x - aout2[rp].x,
                                                   xr2[rp].y - aout2[rp].y);
            } else {
#pragma unroll
                for (int rp = 0; rp < 2; rp++) {
                    float2 ls = make_float2(0.5f * aout2[rp].x, 0.5f * aout2[rp].y);
                    lssum2[rp].x += ls.x;
                    lssum2[rp].y += ls.y;
                    sI[tb][pair][rp] = make_float2(
                        __fdividef(1.f, __expf(ls.x) + EPSf),
                        __fdividef(1.f, __expf(ls.y) + EPSf));
                }
            }
        }

        cp_wait_all();
        __syncthreads();   // weights for step t ready + exchange visible

        // ---- everyone computes y for the 4 rows (broadcast LDS reads) ----
        const float* pD = (const float*)&sD[tb][pair][0];
        const float* pI = (const float*)&sI[tb][pair][0];
        float2 y2[RPW];
        {
            float4 d0 = ((const float4*)pD)[0];
            float4 i0 = ((const float4*)pI)[0];
            float yv[RPW] = {d0.x * i0.x, d0.y * i0.y, d0.z * i0.z, d0.w * i0.w};
#pragma unroll
            for (int r = 0; r < RPW; r++) y2[r] = make_float2(yv[r], yv[r]);
        }
        // mu-warp lanes 0..3 store y for their row
        if (net == 0 && l < RPW)
            out[(base_row + l) * 32 + j] = pD[l] * pI[l];

        if (t == 32) break;

        if (t < 31) {
            const int tn = t + 1, jn = tn - 1;
            const int offn = (tn <= 9) ? 9 * (tn - 1) : 72 + 8 * (tn - 9);
            if (tn <= 8)       prefetch_step<9, 0>(jn, offn, tid, buf ^ 1, SW0, SW1, SW2);
            else if (tn <= 15) prefetch_step<8, 1>(jn, offn, tid, buf ^ 1, SW0, SW1, SW2);
            else if (tn <= 23) prefetch_step<8, 2>(jn, offn, tid, buf ^ 1, SW0, SW1, SW2);
            else               prefetch_step<8, 3>(jn, offn, tid, buf ^ 1, SW0, SW1, SW2);
            cp_commit();
        }

        const int off = (t <= 9) ? 9 * (t - 1) : 72 + 8 * (t - 9);
        if (t <= 8)
            do_step<9, 0>(l, off, buf, net, y2, a0, a1, aout2, SW0, SW1, SW2, sH0s[w], sH1s[w]);
        else if (t <= 15)
            do_step<8, 1>(l, off, buf, net, y2, a0, a1, aout2, SW0, SW1, SW2, sH0s[w], sH1s[w]);
        else if (t <= 23)
            do_step<8, 2>(l, off, buf, net, y2, a0, a1, aout2, SW0, SW1, SW2, sH0s[w], sH1s[w]);
        else
            do_step<8, 3>(l, off, buf, net, y2, a0, a1, aout2, SW0, SW1, SW2, sH0s[w], sH1s[w]);
        buf ^= 1;
    }

    // ---- logstd row-sums: lv-warp reduces lane-partial sums ----
    if (net == 1) {
#pragma unroll
        for (int rp = 0; rp < 2; rp++) {
            float sx = lssum2[rp].x, sy = lssum2[rp].y;
#pragma unroll
            for (int o = 16; o > 0; o >>= 1) {
                sx += __shfl_xor_sync(0xffffffffu, sx, o);
                sy += __shfl_xor_sync(0xffffffffu, sy, o);
            }
            if (l == 0) {
                out[Bb * Dd + base_row + 2 * rp]     = sx;
                out[Bb * Dd + base_row + 2 * rp + 1] = sy;
            }
        }
    }
}

extern "C" void kernel_launch(void* const* d_in, const int* in_sizes, int n_in,
                              void* d_out, int out_size)
{
    (void)in_sizes; (void)n_in; (void)out_size;
    const float* x = (const float*)d_in[0];

    prep_kernel<<<512, 256>>>(
        (const float*)d_in[1],  (const float*)d_in[2],  (const float*)d_in[3],
        (const float*)d_in[4],  (const float*)d_in[5],  (const float*)d_in[6],
        (const float*)d_in[7],  (const float*)d_in[8],  (const float*)d_in[9],
        (const float*)d_in[10], (const float*)d_in[11], (const float*)d_in[12]);

    const int dyn_smem = (1024 + 9216 + 1152) * 4;   // 45568 B
    cudaFuncSetAttribute(afmade_kernel,
                         cudaFuncAttributeMaxDynamicSharedMemorySize, dyn_smem);
    afmade_kernel<<<GRID, THREADS, dyn_smem>>>(x, (float*)d_out);
}